// round 9
// baseline (speedup 1.0000x reference)
#include <cuda_runtime.h>
#include <cuda_bf16.h>

// CRF negative log-likelihood, fixed shapes. sm_100a.
#define B_ 256
#define S_ 1024
#define T_ 64
#define PF 8   // emission prefetch ring depth; renorm every 4 steps

__device__ float g_diff[B_];

// 128 threads: bat = tid>>6 (2 sequences/block), j = tid&63 (tag).
// Warps 0,1 -> batch 0; warps 2,3 -> batch 1. grid = 128 (one clean wave).
__global__ void __launch_bounds__(128) crf_forward_kernel(
    const float* __restrict__ emissions,   // (B, S, T)
    const int* __restrict__ tags,          // (B, S) int32
    const float* __restrict__ trans,       // (T, T)
    const float* __restrict__ startT,      // (T,)
    const float* __restrict__ endT)        // (T,)
{
    const int tid = threadIdx.x;
    const int bat = tid >> 6;
    const int j   = tid & 63;
    const int b   = 2 * blockIdx.x + bat;

    __shared__ __align__(16) float u[2][2][T_];   // [buf][bat][tag]
    __shared__ float redA[2][T_];
    __shared__ float redB[2][T_];

    // Per-thread column of E = exp(trans).
    float Ecol[T_];
#pragma unroll
    for (int i = 0; i < T_; ++i)
        Ecol[i] = __expf(__ldg(trans + i * T_ + j));

    const float* emb = emissions + (size_t)b * S_ * T_ + j;

    // t = 0: u0 = exp(start + em0)
    float v = __expf(__ldg(startT + j) + __ldg(emb));
    u[0][bat][j] = v;
    double c = 0.0;   // running log-scale; accumulated identically by all threads

    // Prefetch ring: PRE-EXPONENTIATED emissions, slot (t-1)&7, t = 1..8.
    float pf[PF];
#pragma unroll
    for (int k = 0; k < PF; ++k)
        pf[k] = __expf(__ldg(emb + (size_t)(1 + k) * T_));

    __syncthreads();

    int cur = 0;
    int t = 1;

    // Main loop: 127 chunks of 8 steps (t = 1..1016). Guarded prefetch
    // compiles to a predicated LDG (no branch).
#pragma unroll 1
    for (int tb = 0; tb < 127; ++tb) {
#pragma unroll
        for (int k = 0; k < 8; ++k, ++t) {
            float scale_mul = pf[k];
            if (t + PF < S_)
                pf[k] = __expf(__ldg(emb + (size_t)(t + PF) * T_));

            const float* ub = u[cur][bat];

            if ((k & 3) == 0) {                // compile-time under unroll
                float scale = ub[0];           // broadcast LDS
                c += (double)__logf(scale);    // branchless, hidden fp64 chain
                scale_mul *= __frcp_rn(scale);
            }

            // 64-FMA dot, 8 independent chains (depth 8).
            float a0 = 0.f, a1 = 0.f, a2 = 0.f, a3 = 0.f;
            float a4 = 0.f, a5 = 0.f, a6 = 0.f, a7 = 0.f;
            const float4* u4 = reinterpret_cast<const float4*>(ub);
#pragma unroll
            for (int i = 0; i < 8; ++i) {
                float4 x = u4[2 * i + 0];
                float4 y = u4[2 * i + 1];
                a0 = fmaf(x.x, Ecol[8 * i + 0], a0);
                a1 = fmaf(x.y, Ecol[8 * i + 1], a1);
                a2 = fmaf(x.z, Ecol[8 * i + 2], a2);
                a3 = fmaf(x.w, Ecol[8 * i + 3], a3);
                a4 = fmaf(y.x, Ecol[8 * i + 4], a4);
                a5 = fmaf(y.y, Ecol[8 * i + 5], a5);
                a6 = fmaf(y.z, Ecol[8 * i + 6], a6);
                a7 = fmaf(y.w, Ecol[8 * i + 7], a7);
            }
            float s = ((a0 + a1) + (a2 + a3)) + ((a4 + a5) + (a6 + a7));
            v = s * scale_mul;

            cur ^= 1;
            u[cur][bat][j] = v;
            __syncthreads();
        }
    }

    // Remainder: t = 1017..1023 (7 steps), emissions already in pf[0..6].
#pragma unroll
    for (int k = 0; k < 7; ++k, ++t) {
        float scale_mul = pf[k];
        const float* ub = u[cur][bat];

        if ((k & 3) == 0) {
            float scale = ub[0];
            c += (double)__logf(scale);
            scale_mul *= __frcp_rn(scale);
        }

        float a0 = 0.f, a1 = 0.f, a2 = 0.f, a3 = 0.f;
        float a4 = 0.f, a5 = 0.f, a6 = 0.f, a7 = 0.f;
        const float4* u4 = reinterpret_cast<const float4*>(ub);
#pragma unroll
        for (int i = 0; i < 8; ++i) {
            float4 x = u4[2 * i + 0];
            float4 y = u4[2 * i + 1];
            a0 = fmaf(x.x, Ecol[8 * i + 0], a0);
            a1 = fmaf(x.y, Ecol[8 * i + 1], a1);
            a2 = fmaf(x.z, Ecol[8 * i + 2], a2);
            a3 = fmaf(x.w, Ecol[8 * i + 3], a3);
            a4 = fmaf(y.x, Ecol[8 * i + 4], a4);
            a5 = fmaf(y.y, Ecol[8 * i + 5], a5);
            a6 = fmaf(y.z, Ecol[8 * i + 6], a6);
            a7 = fmaf(y.w, Ecol[8 * i + 7], a7);
        }
        float s = ((a0 + a1) + (a2 + a3)) + ((a4 + a5) + (a6 + a7));
        v = s * scale_mul;

        cur ^= 1;
        u[cur][bat][j] = v;
        __syncthreads();
    }

    // partition = c + log(sum_j v_j * exp(end_j))
    redA[bat][j] = v * __expf(__ldg(endT + j));

    // Gold-path score, 64 threads per batch over time steps.
    float sc = 0.f;
    const int* tg = tags + (size_t)b * S_;
    const float* emB = emissions + (size_t)b * S_ * T_;
#pragma unroll 4
    for (int tt = j; tt < S_; tt += T_) {
        int tg0 = tg[tt];
        sc += __ldg(emB + (size_t)tt * T_ + tg0);
        if (tt + 1 < S_) {
            int tg1 = tg[tt + 1];
            sc += __ldg(trans + tg0 * T_ + tg1);
        }
    }
    if (j == 0) {
        sc += __ldg(startT + tg[0]);
        sc += __ldg(endT + tg[S_ - 1]);
    }
    redB[bat][j] = sc;
    __syncthreads();

    if (j == 0) {
        float sumw = 0.f;
        float sums = 0.f;
#pragma unroll
        for (int i = 0; i < T_; ++i) {
            sumw += redA[bat][i];
            sums += redB[bat][i];
        }
        double partition = c + (double)__logf(sumw);
        g_diff[b] = (float)(partition - (double)sums);
    }
}

__global__ void crf_reduce_kernel(float* __restrict__ out)
{
    __shared__ float sh[B_];
    int t = threadIdx.x;
    sh[t] = g_diff[t];
    __syncthreads();
#pragma unroll
    for (int off = B_ / 2; off > 0; off >>= 1) {
        if (t < off) sh[t] += sh[t + off];
        __syncthreads();
    }
    if (t == 0) out[0] = sh[0] / (float)B_;
}

extern "C" void kernel_launch(void* const* d_in, const int* in_sizes, int n_in,
                              void* d_out, int out_size)
{
    const float* emissions = (const float*)d_in[0];
    const int*   tags      = (const int*)d_in[1];
    const float* trans     = (const float*)d_in[2];
    const float* startT    = (const float*)d_in[3];
    const float* endT      = (const float*)d_in[4];
    float* out = (float*)d_out;

    crf_forward_kernel<<<B_ / 2, 128>>>(emissions, tags, trans, startT, endT);
    crf_reduce_kernel<<<1, B_>>>(out);
}

// round 11
// speedup vs baseline: 1.3296x; 1.3296x over previous
#include <cuda_runtime.h>
#include <cuda_bf16.h>

// CRF negative log-likelihood, fixed shapes. sm_100a.
#define B_ 256
#define S_ 1024
#define T_ 64
#define PF 8       // emission prefetch ring depth; renorm every 4 steps
#define HPAD 36    // half-vector stride (32 data + 4 pad -> halves 144B apart)

__device__ float g_diff[B_];

// 256 threads, 2 sequences/block, grid=128 (one clean wave, 1 block/SM).
// bat = tid>>7, r = tid&127, tag = r>>1, half = r&1.
// Warps 0-3 = seq A, warps 4-7 = seq B -> every SMSP hosts one warp of EACH
// sequence: two independent dependency chains hide each other's latency.
__global__ void __launch_bounds__(256) crf_forward_kernel(
    const float* __restrict__ emissions,   // (B, S, T)
    const int* __restrict__ tags,          // (B, S) int32
    const float* __restrict__ trans,       // (T, T)
    const float* __restrict__ startT,      // (T,)
    const float* __restrict__ endT)        // (T,)
{
    const int tid  = threadIdx.x;
    const int bat  = tid >> 7;
    const int r    = tid & 127;
    const int tag  = r >> 1;
    const int half = r & 1;
    const int b    = 2 * blockIdx.x + bat;

    __shared__ __align__(16) float u[2][2][2][HPAD];  // [buf][bat][half-region][HPAD]
    __shared__ float redA[2][T_];
    __shared__ float redB[2][128];

    // Half-column of E = exp(trans): rows [half*32, half*32+32) for this tag.
    float Ecol[32];
#pragma unroll
    for (int i = 0; i < 32; ++i)
        Ecol[i] = __expf(__ldg(trans + (half * 32 + i) * T_ + tag));

    const float* emb = emissions + (size_t)b * S_ * T_ + tag;

    // t = 0: u0 = exp(start + em0)
    float v = __expf(__ldg(startT + tag) + __ldg(emb));
    if (half == 0) u[0][bat][tag >> 5][tag & 31] = v;
    double c = 0.0;   // running log-scale; fp64 ONLY on thread r==0 of each bat

    // Prefetch ring: RAW emissions (exp applied in-step, as in the 152us winner).
    float pf[PF];
#pragma unroll
    for (int k = 0; k < PF; ++k)
        pf[k] = __ldg(emb + (size_t)(1 + k) * T_);

    __syncthreads();

    int cur = 0;
    int t = 1;

#pragma unroll 1
    for (int tb = 0; tb < 127; ++tb) {
#pragma unroll
        for (int k = 0; k < 8; ++k, ++t) {
            float em_t = pf[k];
            if (t + PF < S_)
                pf[k] = __ldg(emb + (size_t)(t + PF) * T_);

            const float* ub = u[cur][bat][half];

            float scale_mul = __expf(em_t);
            if ((k & 3) == 0) {                       // compile-time under unroll
                float scale = u[cur][bat][0][0];      // broadcast LDS
                if (r == 0) c += (double)__logf(scale);  // single thread, predicated
                scale_mul *= __frcp_rn(scale);
            }

            // Half-dot: 32 scalar FMAs, 4 chains (depth 8), 8 LDS.128 conflict-free.
            float a0 = 0.f, a1 = 0.f, a2 = 0.f, a3 = 0.f;
            const float4* u4 = reinterpret_cast<const float4*>(ub);
#pragma unroll
            for (int i = 0; i < 8; ++i) {
                float4 uu = u4[i];
                a0 = fmaf(uu.x, Ecol[4 * i + 0], a0);
                a1 = fmaf(uu.y, Ecol[4 * i + 1], a1);
                a2 = fmaf(uu.z, Ecol[4 * i + 2], a2);
                a3 = fmaf(uu.w, Ecol[4 * i + 3], a3);
            }
            float s = (a0 + a1) + (a2 + a3);
            s += __shfl_xor_sync(0xffffffffu, s, 1);   // combine the two halves
            v = s * scale_mul;

            cur ^= 1;
            if (half == 0) u[cur][bat][tag >> 5][tag & 31] = v;
            __syncthreads();
        }
    }
    // Remainder: t = 1017..1023 (7 steps), emissions already in pf[0..6].
#pragma unroll
    for (int k = 0; k < 7; ++k, ++t) {
        float em_t = pf[k];
        const float* ub = u[cur][bat][half];

        float scale_mul = __expf(em_t);
        if ((k & 3) == 0) {
            float scale = u[cur][bat][0][0];
            if (r == 0) c += (double)__logf(scale);
            scale_mul *= __frcp_rn(scale);
        }

        float a0 = 0.f, a1 = 0.f, a2 = 0.f, a3 = 0.f;
        const float4* u4 = reinterpret_cast<const float4*>(ub);
#pragma unroll
        for (int i = 0; i < 8; ++i) {
            float4 uu = u4[i];
            a0 = fmaf(uu.x, Ecol[4 * i + 0], a0);
            a1 = fmaf(uu.y, Ecol[4 * i + 1], a1);
            a2 = fmaf(uu.z, Ecol[4 * i + 2], a2);
            a3 = fmaf(uu.w, Ecol[4 * i + 3], a3);
        }
        float s = (a0 + a1) + (a2 + a3);
        s += __shfl_xor_sync(0xffffffffu, s, 1);
        v = s * scale_mul;

        cur ^= 1;
        if (half == 0) u[cur][bat][tag >> 5][tag & 31] = v;
        __syncthreads();
    }

    // partition = c + log(sum_tag v_tag * exp(end_tag))
    if (half == 0) redA[bat][tag] = v * __expf(__ldg(endT + tag));

    // Gold-path score: 128 threads per sequence over time steps.
    float sc = 0.f;
    const int* tg = tags + (size_t)b * S_;
    const float* emB = emissions + (size_t)b * S_ * T_;
#pragma unroll 2
    for (int tt = r; tt < S_; tt += 128) {
        int tg0 = tg[tt];
        sc += __ldg(emB + (size_t)tt * T_ + tg0);
        if (tt + 1 < S_) {
            int tg1 = tg[tt + 1];
            sc += __ldg(trans + tg0 * T_ + tg1);
        }
    }
    if (r == 0) {
        sc += __ldg(startT + tg[0]);
        sc += __ldg(endT + tg[S_ - 1]);
    }
    redB[bat][r] = sc;
    __syncthreads();

    if (r == 0) {
        float sumw = 0.f;
#pragma unroll
        for (int i = 0; i < T_; ++i) sumw += redA[bat][i];
        float sums = 0.f;
#pragma unroll
        for (int i = 0; i < 128; ++i) sums += redB[bat][i];
        double partition = c + (double)__logf(sumw);
        g_diff[b] = (float)(partition - (double)sums);
    }
}

__global__ void crf_reduce_kernel(float* __restrict__ out)
{
    __shared__ float sh[B_];
    int t = threadIdx.x;
    sh[t] = g_diff[t];
    __syncthreads();
#pragma unroll
    for (int off = B_ / 2; off > 0; off >>= 1) {
        if (t < off) sh[t] += sh[t + off];
        __syncthreads();
    }
    if (t == 0) out[0] = sh[0] / (float)B_;
}

extern "C" void kernel_launch(void* const* d_in, const int* in_sizes, int n_in,
                              void* d_out, int out_size)
{
    const float* emissions = (const float*)d_in[0];
    const int*   tags      = (const int*)d_in[1];
    const float* trans     = (const float*)d_in[2];
    const float* startT    = (const float*)d_in[3];
    const float* endT      = (const float*)d_in[4];
    float* out = (float*)d_out;

    crf_forward_kernel<<<B_ / 2, 256>>>(emissions, tags, trans, startT, endT);
    crf_reduce_kernel<<<1, B_>>>(out);
}